// round 14
// baseline (speedup 1.0000x reference)
#include <cuda_runtime.h>
#include <cuda_bf16.h>
#include <math.h>
#include <stdint.h>

// Problem constants
#define BB 2
#define NN 2048
#define BN 4096          // B*N
#define CC 256
#define HI 64
#define WI 176
#define HW (HI*WI)       // 11264
#define TS 16            // tile size
#define TBX (WI/TS)      // 11
#define TBY (HI/TS)      // 4
#define TPB (TBX*TBY)    // 44 tiles per batch
#define NT (BB*TPB)      // 88 tiles total
#define MAXG 2048
#define FM_SIZE (BB*CC*HW)

// ---------------- device scratch ----------------
// pre-split activations: packed bf16 (hi,lo) pairs along k, layout [M][K2]
__device__ uint32_t a_gh[BN*8],   a_gl[BN*8];     // input g  (K=14 -> 8 pairs padded)
__device__ uint32_t a_1h[BN*32],  a_1l[BN*32];    // h1 (64)
__device__ uint32_t a_2h[BN*64],  a_2l[BN*64];    // h2 (128)
__device__ uint32_t a_3h[BN*128], a_3l[BN*128];   // feats (256)
__device__ uint32_t a_4h[BN*128], a_4l[BN*128];   // ft1 (256)
// pre-split weights: layout [k2][N]
__device__ uint32_t w1h[8*64],    w1l[8*64];
__device__ uint32_t w2h[32*128],  w2l[32*128];
__device__ uint32_t w3h[64*256],  w3l[64*256];
__device__ uint32_t f1h[128*256], f1l[128*256];
__device__ uint32_t f2h[128*256], f2l[128*256];

__device__ float g_featsT[BN*CC];
__device__ float g_px[BN], g_py[BN], g_isx[BN], g_isy[BN], g_w[BN], g_as[BN];
__device__ int   g_tcount[NT];
__device__ int   g_tlist[NT*MAXG];

// ---------------- bf16 helpers ----------------
__device__ __forceinline__ void bfsplit(float x, __nv_bfloat16& h, __nv_bfloat16& l) {
    h = __float2bfloat16(x);
    l = __float2bfloat16(x - __bfloat162float(h));
}
__device__ __forceinline__ uint32_t pkbf(__nv_bfloat16 lo, __nv_bfloat16 hi) {
    __nv_bfloat162 v = __halves2bfloat162(lo, hi);
    return *(uint32_t*)&v;
}
__device__ __forceinline__ void mma_bf16(float* c,
    uint32_t a0, uint32_t a1, uint32_t a2, uint32_t a3,
    uint32_t b0, uint32_t b1)
{
    asm("mma.sync.aligned.m16n8k16.row.col.f32.bf16.bf16.f32 "
        "{%0,%1,%2,%3}, {%4,%5,%6,%7}, {%8,%9}, {%0,%1,%2,%3};"
        : "+f"(c[0]), "+f"(c[1]), "+f"(c[2]), "+f"(c[3])
        : "r"(a0), "r"(a1), "r"(a2), "r"(a3), "r"(b0), "r"(b1));
}

// ---------------- prep: split weights / input into bf16 pairs ----------------
__global__ void prep_w(const float* __restrict__ W, uint32_t* __restrict__ Wh,
                       uint32_t* __restrict__ Wl, int Kd, int Nd, int K2tot) {
    int idx = blockIdx.x * blockDim.x + threadIdx.x;
    if (idx >= K2tot * Nd) return;
    int k2 = idx / Nd, n = idx - k2 * Nd;
    float v0 = (2 * k2     < Kd) ? W[(size_t)(2 * k2)     * Nd + n] : 0.f;
    float v1 = (2 * k2 + 1 < Kd) ? W[(size_t)(2 * k2 + 1) * Nd + n] : 0.f;
    __nv_bfloat16 h0, l0, h1, l1;
    bfsplit(v0, h0, l0); bfsplit(v1, h1, l1);
    Wh[idx] = pkbf(h0, h1);
    Wl[idx] = pkbf(l0, l1);
}

__global__ void prep_g(const float* __restrict__ g) {
    int idx = blockIdx.x * blockDim.x + threadIdx.x;
    if (idx >= BN * 8) return;
    int row = idx >> 3, k2 = idx & 7;
    float v0 = (2 * k2     < 14) ? g[(size_t)row * 14 + 2 * k2]     : 0.f;
    float v1 = (2 * k2 + 1 < 14) ? g[(size_t)row * 14 + 2 * k2 + 1] : 0.f;
    __nv_bfloat16 h0, l0, h1, l1;
    bfsplit(v0, h0, l0); bfsplit(v1, h1, l1);
    a_gh[idx] = pkbf(h0, h1);
    a_gl[idx] = pkbf(l0, l1);
}

// ---------------- projection + binning (fused) ----------------
__global__ void proj_bin_kernel(const float* __restrict__ g, const float* __restrict__ Kin) {
    int i = blockIdx.x * blockDim.x + threadIdx.x;
    if (i >= BN) return;
    const float* gd = g + (size_t)i * 14;
    float x = gd[0], y = gd[1], z = gd[2];
    float k00 = Kin[0], k01 = Kin[1], k02 = Kin[2];
    float k10 = Kin[3], k11 = Kin[4], k12 = Kin[5];
    float k20 = Kin[6], k21 = Kin[7], k22 = Kin[8];
    float pz = k20 * x + k21 * y + k22 * z;
    float denom = pz + 1e-6f;
    float pxn = (k00 * x + k01 * y + k02 * z) / denom;
    float pyn = (k10 * x + k11 * y + k12 * z) / denom;
    float scale_x = (float)WI / k02 * 0.5f;
    float scale_y = (float)HI / k12 * 0.5f;
    float px = pxn * scale_x;
    float py = pyn * scale_y;
    bool valid = (z > 0.1f);
    bool inb = (px >= 0.f) && (px < (float)WI) && (py >= 0.f) && (py < (float)HI);
    bool mask = valid && inb;
    float sx = fmaxf(gd[5] * scale_x, 1.0f);
    float sy = fmaxf(gd[6] * scale_y, 1.0f);
    float w = mask ? gd[12] : 0.0f;
    g_px[i] = px;  g_py[i] = py;
    g_isx[i] = 1.0f / sx;  g_isy[i] = 1.0f / sy;
    g_w[i]  = w;
    g_as[i] = 0.5f * (sx + sy);
    if (w == 0.0f) return;

    float rx = 3.0f * sx;
    float ry = 3.0f * sy;
    int b = i >> 11;
    int tx0 = max(0, (int)floorf((px - rx) * (1.0f / TS)));
    int tx1 = min(TBX - 1, (int)floorf((px + rx) * (1.0f / TS)));
    int ty0 = max(0, (int)floorf((py - ry) * (1.0f / TS)));
    int ty1 = min(TBY - 1, (int)floorf((py + ry) * (1.0f / TS)));
    for (int ty = ty0; ty <= ty1; ty++)
        for (int tx = tx0; tx <= tx1; tx++) {
            int t = b * TPB + ty * TBX + tx;
            int o = atomicAdd(&g_tcount[t], 1);
            if (o < MAXG) g_tlist[t * MAXG + o] = i;
        }
}

// ---------------- pre-split bf16 GEMM: 64x64 tile, double-buffered ----------
// All operands pre-split (hi,lo) bf16 pairs. Per 16-k slab & (mt,nt): 3 MMAs.
// If writeSplit: emit C as pre-split pairs for the next layer; else fp32.
__global__ void __launch_bounds__(256) gemm_bf16p_kernel(
    const uint32_t* __restrict__ Ah, const uint32_t* __restrict__ Al,
    const uint32_t* __restrict__ Wh, const uint32_t* __restrict__ Wl,
    const float* __restrict__ bias,
    uint32_t* __restrict__ Ch, uint32_t* __restrict__ Cl, float* __restrict__ Cf,
    int K2tot, int Nd, int doRelu, int writeSplit)
{
    __shared__ uint32_t Ahp[2][8][136], Alp[2][8][136];   // [buf][k2][m]
    __shared__ uint32_t Bhp[2][8][72],  Blp[2][8][72];    // [buf][k2][n]

    int m0 = blockIdx.x * 64;
    int n0 = blockIdx.y * 64;
    int t = threadIdx.x;
    int lane = t & 31;
    int wid = t >> 5;
    int wm = wid & 1;
    int wn = wid >> 1;
    int g = lane >> 2;
    int c = lane & 3;

    float d[2][2][4];
    #pragma unroll
    for (int mt = 0; mt < 2; mt++)
        #pragma unroll
        for (int nt = 0; nt < 2; nt++)
            #pragma unroll
            for (int i = 0; i < 4; i++) d[mt][nt][i] = 0.f;

    int nkt = K2tot >> 3;
    int arow = t >> 2, ak2 = (t & 3) * 2;     // A: row, 2 consecutive k2
    int bk2 = t >> 5, bn2 = (t & 31) * 2;     // B: k2 row, 2 cols

    uint2 avh, avl, bvh, bvl;
    avh = *(const uint2*)&Ah[(size_t)(m0 + arow) * K2tot + ak2];
    avl = *(const uint2*)&Al[(size_t)(m0 + arow) * K2tot + ak2];
    bvh = *(const uint2*)&Wh[(size_t)bk2 * Nd + n0 + bn2];
    bvl = *(const uint2*)&Wl[(size_t)bk2 * Nd + n0 + bn2];

    for (int kt = 0; kt < nkt; kt++) {
        int buf = kt & 1;
        Ahp[buf][ak2][arow]     = avh.x;
        Ahp[buf][ak2 + 1][arow] = avh.y;
        Alp[buf][ak2][arow]     = avl.x;
        Alp[buf][ak2 + 1][arow] = avl.y;
        *(uint2*)&Bhp[buf][bk2][bn2] = bvh;
        *(uint2*)&Blp[buf][bk2][bn2] = bvl;
        __syncthreads();
        if (kt + 1 < nkt) {
            int kb = (kt + 1) * 8;
            avh = *(const uint2*)&Ah[(size_t)(m0 + arow) * K2tot + kb + ak2];
            avl = *(const uint2*)&Al[(size_t)(m0 + arow) * K2tot + kb + ak2];
            bvh = *(const uint2*)&Wh[(size_t)(kb + bk2) * Nd + n0 + bn2];
            bvl = *(const uint2*)&Wl[(size_t)(kb + bk2) * Nd + n0 + bn2];
        }
        // one k16 mma step
        {
            uint32_t ah[2][4], al[2][4], bh[2][2], bl[2][2];
            #pragma unroll
            for (int mt = 0; mt < 2; mt++) {
                int m = wm * 32 + mt * 16 + g;
                ah[mt][0] = Ahp[buf][c][m];     ah[mt][1] = Ahp[buf][c][m + 8];
                ah[mt][2] = Ahp[buf][c+4][m];   ah[mt][3] = Ahp[buf][c+4][m + 8];
                al[mt][0] = Alp[buf][c][m];     al[mt][1] = Alp[buf][c][m + 8];
                al[mt][2] = Alp[buf][c+4][m];   al[mt][3] = Alp[buf][c+4][m + 8];
            }
            #pragma unroll
            for (int nt = 0; nt < 2; nt++) {
                int n = wn * 16 + nt * 8 + g;
                bh[nt][0] = Bhp[buf][c][n];     bh[nt][1] = Bhp[buf][c+4][n];
                bl[nt][0] = Blp[buf][c][n];     bl[nt][1] = Blp[buf][c+4][n];
            }
            #pragma unroll
            for (int mt = 0; mt < 2; mt++)
                #pragma unroll
                for (int nt = 0; nt < 2; nt++) {
                    mma_bf16(d[mt][nt], ah[mt][0], ah[mt][1], ah[mt][2], ah[mt][3],
                             bh[nt][0], bh[nt][1]);
                    mma_bf16(d[mt][nt], al[mt][0], al[mt][1], al[mt][2], al[mt][3],
                             bh[nt][0], bh[nt][1]);
                    mma_bf16(d[mt][nt], ah[mt][0], ah[mt][1], ah[mt][2], ah[mt][3],
                             bl[nt][0], bl[nt][1]);
                }
        }
        __syncthreads();
    }

    // epilogue: bias + relu; emit split pairs (cols 2c,2c+1 adjacent) or fp32
    int K2o = Nd >> 1;
    #pragma unroll
    for (int nt = 0; nt < 2; nt++) {
        int col = n0 + wn * 16 + nt * 8 + c * 2;
        float2 bv2 = *(const float2*)&bias[col];
        #pragma unroll
        for (int mt = 0; mt < 2; mt++) {
            int row0 = m0 + wm * 32 + mt * 16 + g;
            float2 o0 = make_float2(d[mt][nt][0] + bv2.x, d[mt][nt][1] + bv2.y);
            float2 o1 = make_float2(d[mt][nt][2] + bv2.x, d[mt][nt][3] + bv2.y);
            if (doRelu) {
                o0.x = fmaxf(o0.x, 0.f); o0.y = fmaxf(o0.y, 0.f);
                o1.x = fmaxf(o1.x, 0.f); o1.y = fmaxf(o1.y, 0.f);
            }
            if (writeSplit) {
                int colp = (col >> 1);
                __nv_bfloat16 h0, l0, h1, l1;
                bfsplit(o0.x, h0, l0); bfsplit(o0.y, h1, l1);
                Ch[(size_t)row0 * K2o + colp] = pkbf(h0, h1);
                Cl[(size_t)row0 * K2o + colp] = pkbf(l0, l1);
                bfsplit(o1.x, h0, l0); bfsplit(o1.y, h1, l1);
                Ch[(size_t)(row0 + 8) * K2o + colp] = pkbf(h0, h1);
                Cl[(size_t)(row0 + 8) * K2o + colp] = pkbf(l0, l1);
            } else {
                *(float2*)&Cf[(size_t)row0 * Nd + col]       = o0;
                *(float2*)&Cf[(size_t)(row0 + 8) * Nd + col] = o1;
            }
        }
    }
}

// ---------------- tile render: 4 slices x 64 ch, bf16 2-split MMA -------------
__global__ void __launch_bounds__(256, 2) render_kernel(float* __restrict__ out) {
    int tile = blockIdx.x;
    int slice = blockIdx.y;
    int b = tile / TPB;
    int tl = tile % TPB;
    int tx0 = (tl % TBX) * TS;
    int ty0 = (tl / TBX) * TS;
    int t = threadIdx.x;
    int lx = t & 15;
    int ly = t >> 4;
    int lane = t & 31;
    int wid = t >> 5;
    int wm = wid & 1;
    int wn = wid >> 1;
    int g = lane >> 2;
    int c = lane & 3;

    __shared__ float s_px[16], s_py[16], s_isx[16], s_isy[16], s_w[16], s_as[16];
    __shared__ int   s_n[16];
    __shared__ float s_dx2[16][16], s_dy2[16][16], s_ex[16][16], s_ey[16][16];
    __shared__ uint32_t s_gwh[8][264], s_gwl[8][264];
    __shared__ uint32_t s_Fh[8][136], s_Fl[8][136];

    float* s_d = &s_dx2[0][0];

    float d[2][8][4];
    #pragma unroll
    for (int mt = 0; mt < 2; mt++)
        #pragma unroll
        for (int nt = 0; nt < 8; nt++)
            #pragma unroll
            for (int i = 0; i < 4; i++) d[mt][nt][i] = 0.f;
    float dacc = 0.f, uacc = 0.f;

    int K = g_tcount[tile];
    if (K > MAXG) K = MAXG;

    for (int c0 = 0; c0 < K; c0 += 16) {
        if (t < 16) {
            int idx = c0 + t;
            if (idx < K) {
                int n = g_tlist[tile * MAXG + idx];
                s_n[t] = n;
                s_px[t] = g_px[n];   s_py[t] = g_py[n];
                s_isx[t] = g_isx[n]; s_isy[t] = g_isy[n];
                s_w[t] = g_w[n];     s_as[t] = g_as[n];
            } else {
                s_n[t] = 0;
                s_px[t] = 3e8f; s_py[t] = 3e8f;
                s_isx[t] = 1.f; s_isy[t] = 1.f;
                s_w[t] = 0.f;   s_as[t] = 0.f;
            }
        }
        __syncthreads();
        // F slice: 16 gaussians x 64 channels -> bf16 pairs along j
        {
            int j2 = t >> 5;
            int ch2 = (t & 31) * 2;
            int ne = s_n[2 * j2], no = s_n[2 * j2 + 1];
            float2 fe = *(const float2*)&g_featsT[(size_t)ne * CC + slice * 64 + ch2];
            float2 fo = *(const float2*)&g_featsT[(size_t)no * CC + slice * 64 + ch2];
            __nv_bfloat16 he, le, ho, lo;
            bfsplit(fe.x, he, le); bfsplit(fo.x, ho, lo);
            s_Fh[j2][ch2]   = pkbf(he, ho);
            s_Fl[j2][ch2]   = pkbf(le, lo);
            bfsplit(fe.y, he, le); bfsplit(fo.y, ho, lo);
            s_Fh[j2][ch2+1] = pkbf(he, ho);
            s_Fl[j2][ch2+1] = pkbf(le, lo);
        }
        // separable exp
        {
            int j = t >> 4, i2 = t & 15;
            float dx = ((float)(tx0 + i2) - s_px[j]) * s_isx[j];
            float dx2 = dx * dx;
            s_dx2[j][i2] = dx2;
            s_ex[j][i2] = __expf(-0.5f * dx2);
            float dy = ((float)(ty0 + i2) - s_py[j]) * s_isy[j];
            float dy2 = dy * dy;
            s_dy2[j][i2] = dy2;
            s_ey[j][i2] = __expf(-0.5f * dy2);
        }
        __syncthreads();
        // gw for my pixel across 16 gaussians (exact fp32 density)
        #pragma unroll
        for (int j2 = 0; j2 < 8; j2++) {
            int j0 = 2 * j2, j1 = 2 * j2 + 1;
            float dd0 = s_dx2[j0][lx] + s_dy2[j0][ly];
            float dd1 = s_dx2[j1][lx] + s_dy2[j1][ly];
            float g0 = (dd0 < 9.0f) ? s_w[j0] * s_ex[j0][lx] * s_ey[j0][ly] : 0.0f;
            float g1 = (dd1 < 9.0f) ? s_w[j1] * s_ex[j1][lx] * s_ey[j1][ly] : 0.0f;
            dacc += g0 + g1;
            uacc += g0 * s_as[j0] + g1 * s_as[j1];
            __nv_bfloat16 h0, l0, h1, l1;
            bfsplit(g0, h0, l0); bfsplit(g1, h1, l1);
            s_gwh[j2][t] = pkbf(h0, h1);
            s_gwl[j2][t] = pkbf(l0, l1);
        }
        __syncthreads();
        // one k16 mma slab: 2 mt x 8 nt x 3 terms
        {
            uint32_t ah[2][4], al[2][4];
            #pragma unroll
            for (int mt = 0; mt < 2; mt++) {
                int m = wm * 32 + mt * 16 + g;
                ah[mt][0] = s_Fh[c][m];     ah[mt][1] = s_Fh[c][m + 8];
                ah[mt][2] = s_Fh[c+4][m];   ah[mt][3] = s_Fh[c+4][m + 8];
                al[mt][0] = s_Fl[c][m];     al[mt][1] = s_Fl[c][m + 8];
                al[mt][2] = s_Fl[c+4][m];   al[mt][3] = s_Fl[c+4][m + 8];
            }
            #pragma unroll
            for (int nt = 0; nt < 8; nt++) {
                int n = wn * 64 + nt * 8 + g;
                uint32_t bh0 = s_gwh[c][n],   bh1 = s_gwh[c+4][n];
                uint32_t bl0 = s_gwl[c][n],   bl1 = s_gwl[c+4][n];
                #pragma unroll
                for (int mt = 0; mt < 2; mt++) {
                    mma_bf16(d[mt][nt], ah[mt][0], ah[mt][1], ah[mt][2], ah[mt][3], bh0, bh1);
                    mma_bf16(d[mt][nt], al[mt][0], al[mt][1], al[mt][2], al[mt][3], bh0, bh1);
                    mma_bf16(d[mt][nt], ah[mt][0], ah[mt][1], ah[mt][2], ah[mt][3], bl0, bl1);
                }
            }
        }
        __syncthreads();
    }

    s_d[t] = dacc;
    __syncthreads();

    #pragma unroll
    for (int nt = 0; nt < 8; nt++) {
        int n = wn * 64 + nt * 8 + c * 2;
        float inv0 = 1.0f / fmaxf(s_d[n], 1e-6f);
        float inv1 = 1.0f / fmaxf(s_d[n + 1], 1e-6f);
        int py = n >> 4;
        int pxx = n & 15;
        #pragma unroll
        for (int mt = 0; mt < 2; mt++) {
            int ch = slice * 64 + wm * 32 + mt * 16 + g;
            float* r0 = out + (((size_t)(b * CC + ch) * HI + ty0 + py) * WI + tx0 + pxx);
            float* r1 = out + (((size_t)(b * CC + ch + 8) * HI + ty0 + py) * WI + tx0 + pxx);
            *(float2*)r0 = make_float2(d[mt][nt][0] * inv0, d[mt][nt][1] * inv1);
            *(float2*)r1 = make_float2(d[mt][nt][2] * inv0, d[mt][nt][3] * inv1);
        }
    }
    if (slice == 0) {
        int pix = (ty0 + ly) * WI + tx0 + lx;
        float dv = fmaxf(dacc, 1e-6f);
        out[FM_SIZE + b * HW + pix] = uacc / dv;
        out[FM_SIZE + BB * HW + b * HW + pix] = dv;
    }
}

// ---------------- launch ----------------
extern "C" void kernel_launch(void* const* d_in, const int* in_sizes, int n_in,
                              void* d_out, int out_size) {
    const float* g      = (const float*)d_in[0];
    const float* intr   = (const float*)d_in[1];
    const float* enc_w1 = (const float*)d_in[2];
    const float* enc_b1 = (const float*)d_in[3];
    const float* enc_w2 = (const float*)d_in[4];
    const float* enc_b2 = (const float*)d_in[5];
    const float* enc_w3 = (const float*)d_in[6];
    const float* enc_b3 = (const float*)d_in[7];
    const float* ft_w1  = (const float*)d_in[8];
    const float* ft_b1  = (const float*)d_in[9];
    const float* ft_w2  = (const float*)d_in[10];
    const float* ft_b2  = (const float*)d_in[11];
    float* out = (float*)d_out;

    uint32_t *pagh, *pagl, *pa1h, *pa1l, *pa2h, *pa2l, *pa3h, *pa3l, *pa4h, *pa4l;
    uint32_t *pw1h, *pw1l, *pw2h, *pw2l, *pw3h, *pw3l, *pf1h, *pf1l, *pf2h, *pf2l;
    float *pfeatsT;
    int *ptc;
    cudaGetSymbolAddress((void**)&pagh, a_gh);  cudaGetSymbolAddress((void**)&pagl, a_gl);
    cudaGetSymbolAddress((void**)&pa1h, a_1h);  cudaGetSymbolAddress((void**)&pa1l, a_1l);
    cudaGetSymbolAddress((void**)&pa2h, a_2h);  cudaGetSymbolAddress((void**)&pa2l, a_2l);
    cudaGetSymbolAddress((void**)&pa3h, a_3h);  cudaGetSymbolAddress((void**)&pa3l, a_3l);
    cudaGetSymbolAddress((void**)&pa4h, a_4h);  cudaGetSymbolAddress((void**)&pa4l, a_4l);
    cudaGetSymbolAddress((void**)&pw1h, w1h);   cudaGetSymbolAddress((void**)&pw1l, w1l);
    cudaGetSymbolAddress((void**)&pw2h, w2h);   cudaGetSymbolAddress((void**)&pw2l, w2l);
    cudaGetSymbolAddress((void**)&pw3h, w3h);   cudaGetSymbolAddress((void**)&pw3l, w3l);
    cudaGetSymbolAddress((void**)&pf1h, f1h);   cudaGetSymbolAddress((void**)&pf1l, f1l);
    cudaGetSymbolAddress((void**)&pf2h, f2h);   cudaGetSymbolAddress((void**)&pf2l, f2l);
    cudaGetSymbolAddress((void**)&pfeatsT, g_featsT);
    cudaGetSymbolAddress((void**)&ptc, g_tcount);

    cudaMemsetAsync(ptc, 0, NT * sizeof(int));
    proj_bin_kernel<<<(BN + 255) / 256, 256>>>(g, intr);

    // prep: split inputs/weights
    prep_g<<<(BN * 8 + 255) / 256, 256>>>(g);
    prep_w<<<(8 * 64 + 255) / 256, 256>>>(enc_w1, pw1h, pw1l, 14, 64, 8);
    prep_w<<<(32 * 128 + 255) / 256, 256>>>(enc_w2, pw2h, pw2l, 64, 128, 32);
    prep_w<<<(64 * 256 + 255) / 256, 256>>>(enc_w3, pw3h, pw3l, 128, 256, 64);
    prep_w<<<(128 * 256 + 255) / 256, 256>>>(ft_w1, pf1h, pf1l, 256, 256, 128);
    prep_w<<<(128 * 256 + 255) / 256, 256>>>(ft_w2, pf2h, pf2l, 256, 256, 128);

    // MLP chain (all pre-split; conversion-free inner loops)
    gemm_bf16p_kernel<<<dim3(BN / 64, 1), 256>>>(pagh, pagl, pw1h, pw1l, enc_b1,
                                                 pa1h, pa1l, nullptr, 8, 64, 1, 1);
    gemm_bf16p_kernel<<<dim3(BN / 64, 2), 256>>>(pa1h, pa1l, pw2h, pw2l, enc_b2,
                                                 pa2h, pa2l, nullptr, 32, 128, 1, 1);
    gemm_bf16p_kernel<<<dim3(BN / 64, 4), 256>>>(pa2h, pa2l, pw3h, pw3l, enc_b3,
                                                 pa3h, pa3l, nullptr, 64, 256, 0, 1);
    gemm_bf16p_kernel<<<dim3(BN / 64, 4), 256>>>(pa3h, pa3l, pf1h, pf1l, ft_b1,
                                                 pa4h, pa4l, nullptr, 128, 256, 1, 1);
    gemm_bf16p_kernel<<<dim3(BN / 64, 4), 256>>>(pa4h, pa4l, pf2h, pf2l, ft_b2,
                                                 nullptr, nullptr, pfeatsT, 128, 256, 0, 0);

    render_kernel<<<dim3(NT, 4), 256>>>(out);
}

// round 15
// speedup vs baseline: 1.0633x; 1.0633x over previous
#include <cuda_runtime.h>
#include <cuda_bf16.h>
#include <math.h>
#include <stdint.h>

// Problem constants
#define BB 2
#define NN 2048
#define BN 4096          // B*N
#define CC 256
#define HI 64
#define WI 176
#define HW (HI*WI)       // 11264
#define TS 16            // tile size
#define TBX (WI/TS)      // 11
#define TBY (HI/TS)      // 4
#define TPB (TBX*TBY)    // 44 tiles per batch
#define NT (BB*TPB)      // 88 tiles total
#define MAXG 2048
#define FM_SIZE (BB*CC*HW)

// ---------------- device scratch ----------------
// pre-split activations: packed bf16 (hi,lo) pairs along k, layout [M][K2]
__device__ uint32_t a_gh[BN*8],   a_gl[BN*8];     // input g  (K=14 -> 8 pairs padded)
__device__ uint32_t a_1h[BN*32],  a_1l[BN*32];    // h1 (64)
__device__ uint32_t a_2h[BN*64],  a_2l[BN*64];    // h2 (128)
__device__ uint32_t a_3h[BN*128], a_3l[BN*128];   // feats (256)
__device__ uint32_t a_4h[BN*128], a_4l[BN*128];   // ft1 (256)
// pre-split weights: layout [k2][N]
__device__ uint32_t w1h[8*64],    w1l[8*64];
__device__ uint32_t w2h[32*128],  w2l[32*128];
__device__ uint32_t w3h[64*256],  w3l[64*256];
__device__ uint32_t f1h[128*256], f1l[128*256];
__device__ uint32_t f2h[128*256], f2l[128*256];

__device__ float g_featsT[BN*CC];
__device__ float g_px[BN], g_py[BN], g_isx[BN], g_isy[BN], g_w[BN], g_as[BN];
__device__ int   g_tcount[NT];
__device__ int   g_tlist[NT*MAXG];

// ---------------- bf16 helpers ----------------
__device__ __forceinline__ void bfsplit(float x, __nv_bfloat16& h, __nv_bfloat16& l) {
    h = __float2bfloat16(x);
    l = __float2bfloat16(x - __bfloat162float(h));
}
__device__ __forceinline__ uint32_t pkbf(__nv_bfloat16 lo, __nv_bfloat16 hi) {
    __nv_bfloat162 v = __halves2bfloat162(lo, hi);
    return *(uint32_t*)&v;
}
__device__ __forceinline__ void mma_bf16(float* c,
    uint32_t a0, uint32_t a1, uint32_t a2, uint32_t a3,
    uint32_t b0, uint32_t b1)
{
    asm("mma.sync.aligned.m16n8k16.row.col.f32.bf16.bf16.f32 "
        "{%0,%1,%2,%3}, {%4,%5,%6,%7}, {%8,%9}, {%0,%1,%2,%3};"
        : "+f"(c[0]), "+f"(c[1]), "+f"(c[2]), "+f"(c[3])
        : "r"(a0), "r"(a1), "r"(a2), "r"(a3), "r"(b0), "r"(b1));
}

// ---------------- single fused prep: split input + ALL weights --------------
// Region layout (flat index over pair-elements):
//  [0, 32768)         : input g   (BN rows x 8 pairs, K=14 padded)
//  [32768, 33280)     : w1 (8 x 64,   K=14 padded)
//  [33280, 37376)     : w2 (32 x 128)
//  [37376, 53760)     : w3 (64 x 256)
//  [53760, 86528)     : f1 (128 x 256)
//  [86528, 119296)    : f2 (128 x 256)
#define PREP_TOTAL 119296
__device__ __forceinline__ void split_w_elem(const float* __restrict__ W,
    uint32_t* __restrict__ Wh, uint32_t* __restrict__ Wl,
    int local, int Kd, int Nd)
{
    int k2 = local / Nd, n = local - k2 * Nd;
    float v0 = (2 * k2     < Kd) ? W[(size_t)(2 * k2)     * Nd + n] : 0.f;
    float v1 = (2 * k2 + 1 < Kd) ? W[(size_t)(2 * k2 + 1) * Nd + n] : 0.f;
    __nv_bfloat16 h0, l0, h1, l1;
    bfsplit(v0, h0, l0); bfsplit(v1, h1, l1);
    Wh[local] = pkbf(h0, h1);
    Wl[local] = pkbf(l0, l1);
}

__global__ void prep_all(const float* __restrict__ g,
                         const float* __restrict__ W1, const float* __restrict__ W2,
                         const float* __restrict__ W3, const float* __restrict__ F1,
                         const float* __restrict__ F2)
{
    int idx = blockIdx.x * blockDim.x + threadIdx.x;
    if (idx >= PREP_TOTAL) return;
    if (idx < 32768) {
        int row = idx >> 3, k2 = idx & 7;
        float v0 = (2 * k2     < 14) ? g[(size_t)row * 14 + 2 * k2]     : 0.f;
        float v1 = (2 * k2 + 1 < 14) ? g[(size_t)row * 14 + 2 * k2 + 1] : 0.f;
        __nv_bfloat16 h0, l0, h1, l1;
        bfsplit(v0, h0, l0); bfsplit(v1, h1, l1);
        a_gh[idx] = pkbf(h0, h1);
        a_gl[idx] = pkbf(l0, l1);
    } else if (idx < 33280) {
        split_w_elem(W1, w1h, w1l, idx - 32768, 14, 64);
    } else if (idx < 37376) {
        split_w_elem(W2, w2h, w2l, idx - 33280, 64, 128);
    } else if (idx < 53760) {
        split_w_elem(W3, w3h, w3l, idx - 37376, 128, 256);
    } else if (idx < 86528) {
        split_w_elem(F1, f1h, f1l, idx - 53760, 256, 256);
    } else {
        split_w_elem(F2, f2h, f2l, idx - 86528, 256, 256);
    }
}

// ---------------- projection + binning (fused) ----------------
__global__ void proj_bin_kernel(const float* __restrict__ g, const float* __restrict__ Kin) {
    int i = blockIdx.x * blockDim.x + threadIdx.x;
    if (i >= BN) return;
    const float* gd = g + (size_t)i * 14;
    float x = gd[0], y = gd[1], z = gd[2];
    float k00 = Kin[0], k01 = Kin[1], k02 = Kin[2];
    float k10 = Kin[3], k11 = Kin[4], k12 = Kin[5];
    float k20 = Kin[6], k21 = Kin[7], k22 = Kin[8];
    float pz = k20 * x + k21 * y + k22 * z;
    float denom = pz + 1e-6f;
    float pxn = (k00 * x + k01 * y + k02 * z) / denom;
    float pyn = (k10 * x + k11 * y + k12 * z) / denom;
    float scale_x = (float)WI / k02 * 0.5f;
    float scale_y = (float)HI / k12 * 0.5f;
    float px = pxn * scale_x;
    float py = pyn * scale_y;
    bool valid = (z > 0.1f);
    bool inb = (px >= 0.f) && (px < (float)WI) && (py >= 0.f) && (py < (float)HI);
    bool mask = valid && inb;
    float sx = fmaxf(gd[5] * scale_x, 1.0f);
    float sy = fmaxf(gd[6] * scale_y, 1.0f);
    float w = mask ? gd[12] : 0.0f;
    g_px[i] = px;  g_py[i] = py;
    g_isx[i] = 1.0f / sx;  g_isy[i] = 1.0f / sy;
    g_w[i]  = w;
    g_as[i] = 0.5f * (sx + sy);
    if (w == 0.0f) return;

    float rx = 3.0f * sx;
    float ry = 3.0f * sy;
    int b = i >> 11;
    int tx0 = max(0, (int)floorf((px - rx) * (1.0f / TS)));
    int tx1 = min(TBX - 1, (int)floorf((px + rx) * (1.0f / TS)));
    int ty0 = max(0, (int)floorf((py - ry) * (1.0f / TS)));
    int ty1 = min(TBY - 1, (int)floorf((py + ry) * (1.0f / TS)));
    for (int ty = ty0; ty <= ty1; ty++)
        for (int tx = tx0; tx <= tx1; tx++) {
            int t = b * TPB + ty * TBX + tx;
            int o = atomicAdd(&g_tcount[t], 1);
            if (o < MAXG) g_tlist[t * MAXG + o] = i;
        }
}

// ---------------- pre-split bf16 GEMM: 64x64 tile, double-buffered ----------
// All operands pre-split (hi,lo) bf16 pairs. Per 16-k slab & (mt,nt): 3 MMAs.
// If writeSplit: emit C as pre-split pairs for the next layer; else fp32.
__global__ void __launch_bounds__(256) gemm_bf16p_kernel(
    const uint32_t* __restrict__ Ah, const uint32_t* __restrict__ Al,
    const uint32_t* __restrict__ Wh, const uint32_t* __restrict__ Wl,
    const float* __restrict__ bias,
    uint32_t* __restrict__ Ch, uint32_t* __restrict__ Cl, float* __restrict__ Cf,
    int K2tot, int Nd, int doRelu, int writeSplit)
{
    __shared__ uint32_t Ahp[2][8][136], Alp[2][8][136];   // [buf][k2][m]
    __shared__ uint32_t Bhp[2][8][72],  Blp[2][8][72];    // [buf][k2][n]

    int m0 = blockIdx.x * 64;
    int n0 = blockIdx.y * 64;
    int t = threadIdx.x;
    int lane = t & 31;
    int wid = t >> 5;
    int wm = wid & 1;
    int wn = wid >> 1;
    int g = lane >> 2;
    int c = lane & 3;

    float d[2][2][4];
    #pragma unroll
    for (int mt = 0; mt < 2; mt++)
        #pragma unroll
        for (int nt = 0; nt < 2; nt++)
            #pragma unroll
            for (int i = 0; i < 4; i++) d[mt][nt][i] = 0.f;

    int nkt = K2tot >> 3;
    int arow = t >> 2, ak2 = (t & 3) * 2;     // A: row, 2 consecutive k2
    int bk2 = t >> 5, bn2 = (t & 31) * 2;     // B: k2 row, 2 cols

    uint2 avh, avl, bvh, bvl;
    avh = *(const uint2*)&Ah[(size_t)(m0 + arow) * K2tot + ak2];
    avl = *(const uint2*)&Al[(size_t)(m0 + arow) * K2tot + ak2];
    bvh = *(const uint2*)&Wh[(size_t)bk2 * Nd + n0 + bn2];
    bvl = *(const uint2*)&Wl[(size_t)bk2 * Nd + n0 + bn2];

    for (int kt = 0; kt < nkt; kt++) {
        int buf = kt & 1;
        Ahp[buf][ak2][arow]     = avh.x;
        Ahp[buf][ak2 + 1][arow] = avh.y;
        Alp[buf][ak2][arow]     = avl.x;
        Alp[buf][ak2 + 1][arow] = avl.y;
        *(uint2*)&Bhp[buf][bk2][bn2] = bvh;
        *(uint2*)&Blp[buf][bk2][bn2] = bvl;
        __syncthreads();
        if (kt + 1 < nkt) {
            int kb = (kt + 1) * 8;
            avh = *(const uint2*)&Ah[(size_t)(m0 + arow) * K2tot + kb + ak2];
            avl = *(const uint2*)&Al[(size_t)(m0 + arow) * K2tot + kb + ak2];
            bvh = *(const uint2*)&Wh[(size_t)(kb + bk2) * Nd + n0 + bn2];
            bvl = *(const uint2*)&Wl[(size_t)(kb + bk2) * Nd + n0 + bn2];
        }
        // one k16 mma step
        {
            uint32_t ah[2][4], al[2][4], bh[2][2], bl[2][2];
            #pragma unroll
            for (int mt = 0; mt < 2; mt++) {
                int m = wm * 32 + mt * 16 + g;
                ah[mt][0] = Ahp[buf][c][m];     ah[mt][1] = Ahp[buf][c][m + 8];
                ah[mt][2] = Ahp[buf][c+4][m];   ah[mt][3] = Ahp[buf][c+4][m + 8];
                al[mt][0] = Alp[buf][c][m];     al[mt][1] = Alp[buf][c][m + 8];
                al[mt][2] = Alp[buf][c+4][m];   al[mt][3] = Alp[buf][c+4][m + 8];
            }
            #pragma unroll
            for (int nt = 0; nt < 2; nt++) {
                int n = wn * 16 + nt * 8 + g;
                bh[nt][0] = Bhp[buf][c][n];     bh[nt][1] = Bhp[buf][c+4][n];
                bl[nt][0] = Blp[buf][c][n];     bl[nt][1] = Blp[buf][c+4][n];
            }
            #pragma unroll
            for (int mt = 0; mt < 2; mt++)
                #pragma unroll
                for (int nt = 0; nt < 2; nt++) {
                    mma_bf16(d[mt][nt], ah[mt][0], ah[mt][1], ah[mt][2], ah[mt][3],
                             bh[nt][0], bh[nt][1]);
                    mma_bf16(d[mt][nt], al[mt][0], al[mt][1], al[mt][2], al[mt][3],
                             bh[nt][0], bh[nt][1]);
                    mma_bf16(d[mt][nt], ah[mt][0], ah[mt][1], ah[mt][2], ah[mt][3],
                             bl[nt][0], bl[nt][1]);
                }
        }
        __syncthreads();
    }

    // epilogue: bias + relu; emit split pairs (cols 2c,2c+1 adjacent) or fp32
    int K2o = Nd >> 1;
    #pragma unroll
    for (int nt = 0; nt < 2; nt++) {
        int col = n0 + wn * 16 + nt * 8 + c * 2;
        float2 bv2 = *(const float2*)&bias[col];
        #pragma unroll
        for (int mt = 0; mt < 2; mt++) {
            int row0 = m0 + wm * 32 + mt * 16 + g;
            float2 o0 = make_float2(d[mt][nt][0] + bv2.x, d[mt][nt][1] + bv2.y);
            float2 o1 = make_float2(d[mt][nt][2] + bv2.x, d[mt][nt][3] + bv2.y);
            if (doRelu) {
                o0.x = fmaxf(o0.x, 0.f); o0.y = fmaxf(o0.y, 0.f);
                o1.x = fmaxf(o1.x, 0.f); o1.y = fmaxf(o1.y, 0.f);
            }
            if (writeSplit) {
                int colp = (col >> 1);
                __nv_bfloat16 h0, l0, h1, l1;
                bfsplit(o0.x, h0, l0); bfsplit(o0.y, h1, l1);
                Ch[(size_t)row0 * K2o + colp] = pkbf(h0, h1);
                Cl[(size_t)row0 * K2o + colp] = pkbf(l0, l1);
                bfsplit(o1.x, h0, l0); bfsplit(o1.y, h1, l1);
                Ch[(size_t)(row0 + 8) * K2o + colp] = pkbf(h0, h1);
                Cl[(size_t)(row0 + 8) * K2o + colp] = pkbf(l0, l1);
            } else {
                *(float2*)&Cf[(size_t)row0 * Nd + col]       = o0;
                *(float2*)&Cf[(size_t)(row0 + 8) * Nd + col] = o1;
            }
        }
    }
}

// ---------------- tile render: 4 slices x 64 ch, bf16 2-split MMA -------------
__global__ void __launch_bounds__(256, 2) render_kernel(float* __restrict__ out) {
    int tile = blockIdx.x;
    int slice = blockIdx.y;
    int b = tile / TPB;
    int tl = tile % TPB;
    int tx0 = (tl % TBX) * TS;
    int ty0 = (tl / TBX) * TS;
    int t = threadIdx.x;
    int lx = t & 15;
    int ly = t >> 4;
    int lane = t & 31;
    int wid = t >> 5;
    int wm = wid & 1;
    int wn = wid >> 1;
    int g = lane >> 2;
    int c = lane & 3;

    __shared__ float s_px[16], s_py[16], s_isx[16], s_isy[16], s_w[16], s_as[16];
    __shared__ int   s_n[16];
    __shared__ float s_dx2[16][16], s_dy2[16][16], s_ex[16][16], s_ey[16][16];
    __shared__ uint32_t s_gwh[8][264], s_gwl[8][264];
    __shared__ uint32_t s_Fh[8][136], s_Fl[8][136];

    float* s_d = &s_dx2[0][0];

    float d[2][8][4];
    #pragma unroll
    for (int mt = 0; mt < 2; mt++)
        #pragma unroll
        for (int nt = 0; nt < 8; nt++)
            #pragma unroll
            for (int i = 0; i < 4; i++) d[mt][nt][i] = 0.f;
    float dacc = 0.f, uacc = 0.f;

    int K = g_tcount[tile];
    if (K > MAXG) K = MAXG;

    for (int c0 = 0; c0 < K; c0 += 16) {
        if (t < 16) {
            int idx = c0 + t;
            if (idx < K) {
                int n = g_tlist[tile * MAXG + idx];
                s_n[t] = n;
                s_px[t] = g_px[n];   s_py[t] = g_py[n];
                s_isx[t] = g_isx[n]; s_isy[t] = g_isy[n];
                s_w[t] = g_w[n];     s_as[t] = g_as[n];
            } else {
                s_n[t] = 0;
                s_px[t] = 3e8f; s_py[t] = 3e8f;
                s_isx[t] = 1.f; s_isy[t] = 1.f;
                s_w[t] = 0.f;   s_as[t] = 0.f;
            }
        }
        __syncthreads();
        // F slice: 16 gaussians x 64 channels -> bf16 pairs along j
        {
            int j2 = t >> 5;
            int ch2 = (t & 31) * 2;
            int ne = s_n[2 * j2], no = s_n[2 * j2 + 1];
            float2 fe = *(const float2*)&g_featsT[(size_t)ne * CC + slice * 64 + ch2];
            float2 fo = *(const float2*)&g_featsT[(size_t)no * CC + slice * 64 + ch2];
            __nv_bfloat16 he, le, ho, lo;
            bfsplit(fe.x, he, le); bfsplit(fo.x, ho, lo);
            s_Fh[j2][ch2]   = pkbf(he, ho);
            s_Fl[j2][ch2]   = pkbf(le, lo);
            bfsplit(fe.y, he, le); bfsplit(fo.y, ho, lo);
            s_Fh[j2][ch2+1] = pkbf(he, ho);
            s_Fl[j2][ch2+1] = pkbf(le, lo);
        }
        // separable exp
        {
            int j = t >> 4, i2 = t & 15;
            float dx = ((float)(tx0 + i2) - s_px[j]) * s_isx[j];
            float dx2 = dx * dx;
            s_dx2[j][i2] = dx2;
            s_ex[j][i2] = __expf(-0.5f * dx2);
            float dy = ((float)(ty0 + i2) - s_py[j]) * s_isy[j];
            float dy2 = dy * dy;
            s_dy2[j][i2] = dy2;
            s_ey[j][i2] = __expf(-0.5f * dy2);
        }
        __syncthreads();
        // gw for my pixel across 16 gaussians (exact fp32 density)
        #pragma unroll
        for (int j2 = 0; j2 < 8; j2++) {
            int j0 = 2 * j2, j1 = 2 * j2 + 1;
            float dd0 = s_dx2[j0][lx] + s_dy2[j0][ly];
            float dd1 = s_dx2[j1][lx] + s_dy2[j1][ly];
            float g0 = (dd0 < 9.0f) ? s_w[j0] * s_ex[j0][lx] * s_ey[j0][ly] : 0.0f;
            float g1 = (dd1 < 9.0f) ? s_w[j1] * s_ex[j1][lx] * s_ey[j1][ly] : 0.0f;
            dacc += g0 + g1;
            uacc += g0 * s_as[j0] + g1 * s_as[j1];
            __nv_bfloat16 h0, l0, h1, l1;
            bfsplit(g0, h0, l0); bfsplit(g1, h1, l1);
            s_gwh[j2][t] = pkbf(h0, h1);
            s_gwl[j2][t] = pkbf(l0, l1);
        }
        __syncthreads();
        // one k16 mma slab: 2 mt x 8 nt x 3 terms
        {
            uint32_t ah[2][4], al[2][4];
            #pragma unroll
            for (int mt = 0; mt < 2; mt++) {
                int m = wm * 32 + mt * 16 + g;
                ah[mt][0] = s_Fh[c][m];     ah[mt][1] = s_Fh[c][m + 8];
                ah[mt][2] = s_Fh[c+4][m];   ah[mt][3] = s_Fh[c+4][m + 8];
                al[mt][0] = s_Fl[c][m];     al[mt][1] = s_Fl[c][m + 8];
                al[mt][2] = s_Fl[c+4][m];   al[mt][3] = s_Fl[c+4][m + 8];
            }
            #pragma unroll
            for (int nt = 0; nt < 8; nt++) {
                int n = wn * 64 + nt * 8 + g;
                uint32_t bh0 = s_gwh[c][n],   bh1 = s_gwh[c+4][n];
                uint32_t bl0 = s_gwl[c][n],   bl1 = s_gwl[c+4][n];
                #pragma unroll
                for (int mt = 0; mt < 2; mt++) {
                    mma_bf16(d[mt][nt], ah[mt][0], ah[mt][1], ah[mt][2], ah[mt][3], bh0, bh1);
                    mma_bf16(d[mt][nt], al[mt][0], al[mt][1], al[mt][2], al[mt][3], bh0, bh1);
                    mma_bf16(d[mt][nt], ah[mt][0], ah[mt][1], ah[mt][2], ah[mt][3], bl0, bl1);
                }
            }
        }
        __syncthreads();
    }

    s_d[t] = dacc;
    __syncthreads();

    #pragma unroll
    for (int nt = 0; nt < 8; nt++) {
        int n = wn * 64 + nt * 8 + c * 2;
        float inv0 = 1.0f / fmaxf(s_d[n], 1e-6f);
        float inv1 = 1.0f / fmaxf(s_d[n + 1], 1e-6f);
        int py = n >> 4;
        int pxx = n & 15;
        #pragma unroll
        for (int mt = 0; mt < 2; mt++) {
            int ch = slice * 64 + wm * 32 + mt * 16 + g;
            float* r0 = out + (((size_t)(b * CC + ch) * HI + ty0 + py) * WI + tx0 + pxx);
            float* r1 = out + (((size_t)(b * CC + ch + 8) * HI + ty0 + py) * WI + tx0 + pxx);
            *(float2*)r0 = make_float2(d[mt][nt][0] * inv0, d[mt][nt][1] * inv1);
            *(float2*)r1 = make_float2(d[mt][nt][2] * inv0, d[mt][nt][3] * inv1);
        }
    }
    if (slice == 0) {
        int pix = (ty0 + ly) * WI + tx0 + lx;
        float dv = fmaxf(dacc, 1e-6f);
        out[FM_SIZE + b * HW + pix] = uacc / dv;
        out[FM_SIZE + BB * HW + b * HW + pix] = dv;
    }
}

// ---------------- launch ----------------
extern "C" void kernel_launch(void* const* d_in, const int* in_sizes, int n_in,
                              void* d_out, int out_size) {
    const float* g      = (const float*)d_in[0];
    const float* intr   = (const float*)d_in[1];
    const float* enc_w1 = (const float*)d_in[2];
    const float* enc_b1 = (const float*)d_in[3];
    const float* enc_w2 = (const float*)d_in[4];
    const float* enc_b2 = (const float*)d_in[5];
    const float* enc_w3 = (const float*)d_in[6];
    const float* enc_b3 = (const float*)d_in[7];
    const float* ft_w1  = (const float*)d_in[8];
    const float* ft_b1  = (const float*)d_in[9];
    const float* ft_w2  = (const float*)d_in[10];
    const float* ft_b2  = (const float*)d_in[11];
    float* out = (float*)d_out;

    uint32_t *pagh, *pagl, *pa1h, *pa1l, *pa2h, *pa2l, *pa3h, *pa3l, *pa4h, *pa4l;
    uint32_t *pw1h, *pw1l, *pw2h, *pw2l, *pw3h, *pw3l, *pf1h, *pf1l, *pf2h, *pf2l;
    float *pfeatsT;
    int *ptc;
    cudaGetSymbolAddress((void**)&pagh, a_gh);  cudaGetSymbolAddress((void**)&pagl, a_gl);
    cudaGetSymbolAddress((void**)&pa1h, a_1h);  cudaGetSymbolAddress((void**)&pa1l, a_1l);
    cudaGetSymbolAddress((void**)&pa2h, a_2h);  cudaGetSymbolAddress((void**)&pa2l, a_2l);
    cudaGetSymbolAddress((void**)&pa3h, a_3h);  cudaGetSymbolAddress((void**)&pa3l, a_3l);
    cudaGetSymbolAddress((void**)&pa4h, a_4h);  cudaGetSymbolAddress((void**)&pa4l, a_4l);
    cudaGetSymbolAddress((void**)&pw1h, w1h);   cudaGetSymbolAddress((void**)&pw1l, w1l);
    cudaGetSymbolAddress((void**)&pw2h, w2h);   cudaGetSymbolAddress((void**)&pw2l, w2l);
    cudaGetSymbolAddress((void**)&pw3h, w3h);   cudaGetSymbolAddress((void**)&pw3l, w3l);
    cudaGetSymbolAddress((void**)&pf1h, f1h);   cudaGetSymbolAddress((void**)&pf1l, f1l);
    cudaGetSymbolAddress((void**)&pf2h, f2h);   cudaGetSymbolAddress((void**)&pf2l, f2l);
    cudaGetSymbolAddress((void**)&pfeatsT, g_featsT);
    cudaGetSymbolAddress((void**)&ptc, g_tcount);

    cudaMemsetAsync(ptc, 0, NT * sizeof(int));

    // one fused prep launch: input split + all weight splits
    prep_all<<<(PREP_TOTAL + 255) / 256, 256>>>(g, enc_w1, enc_w2, enc_w3, ft_w1, ft_w2);

    proj_bin_kernel<<<(BN + 255) / 256, 256>>>(g, intr);

    // MLP chain (all pre-split; conversion-free inner loops)
    gemm_bf16p_kernel<<<dim3(BN / 64, 1), 256>>>(pagh, pagl, pw1h, pw1l, enc_b1,
                                                 pa1h, pa1l, nullptr, 8, 64, 1, 1);
    gemm_bf16p_kernel<<<dim3(BN / 64, 2), 256>>>(pa1h, pa1l, pw2h, pw2l, enc_b2,
                                                 pa2h, pa2l, nullptr, 32, 128, 1, 1);
    gemm_bf16p_kernel<<<dim3(BN / 64, 4), 256>>>(pa2h, pa2l, pw3h, pw3l, enc_b3,
                                                 pa3h, pa3l, nullptr, 64, 256, 0, 1);
    gemm_bf16p_kernel<<<dim3(BN / 64, 4), 256>>>(pa3h, pa3l, pf1h, pf1l, ft_b1,
                                                 pa4h, pa4l, nullptr, 128, 256, 1, 1);
    gemm_bf16p_kernel<<<dim3(BN / 64, 4), 256>>>(pa4h, pa4l, pf2h, pf2l, ft_b2,
                                                 nullptr, nullptr, pfeatsT, 128, 256, 0, 0);

    render_kernel<<<dim3(NT, 4), 256>>>(out);
}

// round 16
// speedup vs baseline: 1.1132x; 1.0469x over previous
#include <cuda_runtime.h>
#include <cuda_bf16.h>
#include <math.h>
#include <stdint.h>

// Problem constants
#define BB 2
#define NN 2048
#define BN 4096          // B*N
#define CC 256
#define HI 64
#define WI 176
#define HW (HI*WI)       // 11264
#define TS 16            // tile size
#define TBX (WI/TS)      // 11
#define TBY (HI/TS)      // 4
#define TPB (TBX*TBY)    // 44 tiles per batch
#define NT (BB*TPB)      // 88 tiles total
#define MAXG 2048
#define FM_SIZE (BB*CC*HW)

// ---------------- device scratch ----------------
// pre-split input activations: packed bf16 (hi,lo) pairs along k, layout [M][K2]
__device__ uint32_t a_gh[BN*8], a_gl[BN*8];       // input g (K=14 -> 8 pairs padded)
// pre-split weights: layout [k2][N]
__device__ uint32_t w1h[8*64],    w1l[8*64];
__device__ uint32_t w2h[32*128],  w2l[32*128];
__device__ uint32_t w3h[64*256],  w3l[64*256];
__device__ uint32_t f1h[128*256], f1l[128*256];
__device__ uint32_t f2h[128*256], f2l[128*256];

__device__ float g_featsT[BN*CC];
__device__ float g_px[BN], g_py[BN], g_isx[BN], g_isy[BN], g_w[BN], g_as[BN];
__device__ int   g_tcount[NT];
__device__ int   g_tlist[NT*MAXG];

// ---------------- bf16 helpers ----------------
__device__ __forceinline__ void bfsplit(float x, __nv_bfloat16& h, __nv_bfloat16& l) {
    h = __float2bfloat16(x);
    l = __float2bfloat16(x - __bfloat162float(h));
}
__device__ __forceinline__ uint32_t pkbf(__nv_bfloat16 lo, __nv_bfloat16 hi) {
    __nv_bfloat162 v = __halves2bfloat162(lo, hi);
    return *(uint32_t*)&v;
}
__device__ __forceinline__ void mma_bf16(float* c,
    uint32_t a0, uint32_t a1, uint32_t a2, uint32_t a3,
    uint32_t b0, uint32_t b1)
{
    asm("mma.sync.aligned.m16n8k16.row.col.f32.bf16.bf16.f32 "
        "{%0,%1,%2,%3}, {%4,%5,%6,%7}, {%8,%9}, {%0,%1,%2,%3};"
        : "+f"(c[0]), "+f"(c[1]), "+f"(c[2]), "+f"(c[3])
        : "r"(a0), "r"(a1), "r"(a2), "r"(a3), "r"(b0), "r"(b1));
}

// ---------------- single fused prep: split input + ALL weights --------------
#define PREP_TOTAL 119296
__device__ __forceinline__ void split_w_elem(const float* __restrict__ W,
    uint32_t* __restrict__ Wh, uint32_t* __restrict__ Wl,
    int local, int Kd, int Nd)
{
    int k2 = local / Nd, n = local - k2 * Nd;
    float v0 = (2 * k2     < Kd) ? W[(size_t)(2 * k2)     * Nd + n] : 0.f;
    float v1 = (2 * k2 + 1 < Kd) ? W[(size_t)(2 * k2 + 1) * Nd + n] : 0.f;
    __nv_bfloat16 h0, l0, h1, l1;
    bfsplit(v0, h0, l0); bfsplit(v1, h1, l1);
    Wh[local] = pkbf(h0, h1);
    Wl[local] = pkbf(l0, l1);
}

__global__ void prep_all(const float* __restrict__ g,
                         const float* __restrict__ W1, const float* __restrict__ W2,
                         const float* __restrict__ W3, const float* __restrict__ F1,
                         const float* __restrict__ F2)
{
    int idx = blockIdx.x * blockDim.x + threadIdx.x;
    if (idx >= PREP_TOTAL) return;
    if (idx < 32768) {
        int row = idx >> 3, k2 = idx & 7;
        float v0 = (2 * k2     < 14) ? g[(size_t)row * 14 + 2 * k2]     : 0.f;
        float v1 = (2 * k2 + 1 < 14) ? g[(size_t)row * 14 + 2 * k2 + 1] : 0.f;
        __nv_bfloat16 h0, l0, h1, l1;
        bfsplit(v0, h0, l0); bfsplit(v1, h1, l1);
        a_gh[idx] = pkbf(h0, h1);
        a_gl[idx] = pkbf(l0, l1);
    } else if (idx < 33280) {
        split_w_elem(W1, w1h, w1l, idx - 32768, 14, 64);
    } else if (idx < 37376) {
        split_w_elem(W2, w2h, w2l, idx - 33280, 64, 128);
    } else if (idx < 53760) {
        split_w_elem(W3, w3h, w3l, idx - 37376, 128, 256);
    } else if (idx < 86528) {
        split_w_elem(F1, f1h, f1l, idx - 53760, 256, 256);
    } else {
        split_w_elem(F2, f2h, f2l, idx - 86528, 256, 256);
    }
}

// ---------------- projection + binning (fused) ----------------
__global__ void proj_bin_kernel(const float* __restrict__ g, const float* __restrict__ Kin) {
    int i = blockIdx.x * blockDim.x + threadIdx.x;
    if (i >= BN) return;
    const float* gd = g + (size_t)i * 14;
    float x = gd[0], y = gd[1], z = gd[2];
    float k00 = Kin[0], k01 = Kin[1], k02 = Kin[2];
    float k10 = Kin[3], k11 = Kin[4], k12 = Kin[5];
    float k20 = Kin[6], k21 = Kin[7], k22 = Kin[8];
    float pz = k20 * x + k21 * y + k22 * z;
    float denom = pz + 1e-6f;
    float pxn = (k00 * x + k01 * y + k02 * z) / denom;
    float pyn = (k10 * x + k11 * y + k12 * z) / denom;
    float scale_x = (float)WI / k02 * 0.5f;
    float scale_y = (float)HI / k12 * 0.5f;
    float px = pxn * scale_x;
    float py = pyn * scale_y;
    bool valid = (z > 0.1f);
    bool inb = (px >= 0.f) && (px < (float)WI) && (py >= 0.f) && (py < (float)HI);
    bool mask = valid && inb;
    float sx = fmaxf(gd[5] * scale_x, 1.0f);
    float sy = fmaxf(gd[6] * scale_y, 1.0f);
    float w = mask ? gd[12] : 0.0f;
    g_px[i] = px;  g_py[i] = py;
    g_isx[i] = 1.0f / sx;  g_isy[i] = 1.0f / sy;
    g_w[i]  = w;
    g_as[i] = 0.5f * (sx + sy);
    if (w == 0.0f) return;

    float rx = 3.0f * sx;
    float ry = 3.0f * sy;
    int b = i >> 11;
    int tx0 = max(0, (int)floorf((px - rx) * (1.0f / TS)));
    int tx1 = min(TBX - 1, (int)floorf((px + rx) * (1.0f / TS)));
    int ty0 = max(0, (int)floorf((py - ry) * (1.0f / TS)));
    int ty1 = min(TBY - 1, (int)floorf((py + ry) * (1.0f / TS)));
    for (int ty = ty0; ty <= ty1; ty++)
        for (int tx = tx0; tx <= tx1; tx++) {
            int t = b * TPB + ty * TBX + tx;
            int o = atomicAdd(&g_tcount[t], 1);
            if (o < MAXG) g_tlist[t * MAXG + o] = i;
        }
}

// ---------------- fused MLP: all 5 layers in one kernel ----------------------
// Block = 32 rows carried through all layers in smem (bf16 hi/lo pairs,
// [k2][m] layout, stride 40 -> conflict-free A-fragments). Weights streamed
// through double-buffered smem tiles ([k2][n], stride 264) with reg prefetch.
// 256 threads = 8 warps: wm in {0,1} (m16 tile), wn in {0..3} (N/4 cols).
#define ACT_STRIDE 40
#define WB_STRIDE 264
#define SM_A0H 0
#define SM_A0L 5120
#define SM_A1H 10240
#define SM_A1L 15360
#define SM_WBH 20480
#define SM_WBL 24704
#define MLP_SMEM_U32 28928
#define MLP_SMEM_BYTES (MLP_SMEM_U32 * 4)

template<int K2IN, int N, bool RELU, bool LAST>
__device__ __forceinline__ void mlp_layer(
    const uint32_t* __restrict__ aih, const uint32_t* __restrict__ ail,
    uint32_t* __restrict__ aoh, uint32_t* __restrict__ aol,
    uint32_t* __restrict__ wbh, uint32_t* __restrict__ wbl,
    const uint32_t* __restrict__ Wh, const uint32_t* __restrict__ Wl,
    const float* __restrict__ bias, float* __restrict__ outF,
    int m0, int t)
{
    constexpr int NKT = K2IN / 8;
    constexpr int CNT = N / 32;      // u32 per thread per (h|l) per weight tile
    int lane = t & 31, wid = t >> 5;
    int wm = wid & 1, wn = wid >> 1;
    int g = lane >> 2, c = lane & 3;

    float d[CNT][4];
    #pragma unroll
    for (int nt = 0; nt < CNT; nt++)
        #pragma unroll
        for (int i = 0; i < 4; i++) d[nt][i] = 0.f;

    int wrow = t >> 5;               // tile-local k2 row 0..7
    int wcol = (t & 31) * CNT;

    uint32_t wrh[CNT], wrl[CNT];
    // prefetch weight tile 0
    {
        const uint32_t* ph = &Wh[(size_t)wrow * N + wcol];
        const uint32_t* pl = &Wl[(size_t)wrow * N + wcol];
        #pragma unroll
        for (int i = 0; i < CNT; i += 2) {
            uint2 vh = *(const uint2*)(ph + i); wrh[i] = vh.x; wrh[i + 1] = vh.y;
            uint2 vl = *(const uint2*)(pl + i); wrl[i] = vl.x; wrl[i + 1] = vl.y;
        }
    }

    for (int kt = 0; kt < NKT; kt++) {
        int buf = kt & 1;
        uint32_t* sh = wbh + buf * 2112 + wrow * WB_STRIDE + wcol;
        uint32_t* sl = wbl + buf * 2112 + wrow * WB_STRIDE + wcol;
        #pragma unroll
        for (int i = 0; i < CNT; i += 2) {
            *(uint2*)(sh + i) = make_uint2(wrh[i], wrh[i + 1]);
            *(uint2*)(sl + i) = make_uint2(wrl[i], wrl[i + 1]);
        }
        __syncthreads();
        if (kt + 1 < NKT) {
            const uint32_t* ph = &Wh[(size_t)((kt + 1) * 8 + wrow) * N + wcol];
            const uint32_t* pl = &Wl[(size_t)((kt + 1) * 8 + wrow) * N + wcol];
            #pragma unroll
            for (int i = 0; i < CNT; i += 2) {
                uint2 vh = *(const uint2*)(ph + i); wrh[i] = vh.x; wrh[i + 1] = vh.y;
                uint2 vl = *(const uint2*)(pl + i); wrl[i] = vl.x; wrl[i + 1] = vl.y;
            }
        }
        // A fragments (validated R13 pattern)
        int m = wm * 16 + g;
        uint32_t ah0 = aih[(kt * 8 + c) * ACT_STRIDE + m];
        uint32_t ah1 = aih[(kt * 8 + c) * ACT_STRIDE + m + 8];
        uint32_t ah2 = aih[(kt * 8 + c + 4) * ACT_STRIDE + m];
        uint32_t ah3 = aih[(kt * 8 + c + 4) * ACT_STRIDE + m + 8];
        uint32_t al0 = ail[(kt * 8 + c) * ACT_STRIDE + m];
        uint32_t al1 = ail[(kt * 8 + c) * ACT_STRIDE + m + 8];
        uint32_t al2 = ail[(kt * 8 + c + 4) * ACT_STRIDE + m];
        uint32_t al3 = ail[(kt * 8 + c + 4) * ACT_STRIDE + m + 8];
        const uint32_t* bh_s = wbh + buf * 2112;
        const uint32_t* bl_s = wbl + buf * 2112;
        #pragma unroll
        for (int nt = 0; nt < CNT; nt++) {
            int n = wn * (N / 4) + nt * 8 + g;
            uint32_t b0h = bh_s[c * WB_STRIDE + n];
            uint32_t b1h = bh_s[(c + 4) * WB_STRIDE + n];
            uint32_t b0l = bl_s[c * WB_STRIDE + n];
            uint32_t b1l = bl_s[(c + 4) * WB_STRIDE + n];
            mma_bf16(d[nt], ah0, ah1, ah2, ah3, b0h, b1h);
            mma_bf16(d[nt], al0, al1, al2, al3, b0h, b1h);
            mma_bf16(d[nt], ah0, ah1, ah2, ah3, b0l, b1l);
        }
    }

    // epilogue: bias + relu; write next layer's act (split pairs) or fp32 out
    #pragma unroll
    for (int nt = 0; nt < CNT; nt++) {
        int col = wn * (N / 4) + nt * 8 + c * 2;
        float2 bv = *(const float2*)&bias[col];
        int row0 = wm * 16 + g;
        float o0 = d[nt][0] + bv.x, o1 = d[nt][1] + bv.y;   // row0
        float o2 = d[nt][2] + bv.x, o3 = d[nt][3] + bv.y;   // row0+8
        if (RELU) {
            o0 = fmaxf(o0, 0.f); o1 = fmaxf(o1, 0.f);
            o2 = fmaxf(o2, 0.f); o3 = fmaxf(o3, 0.f);
        }
        if (LAST) {
            *(float2*)&outF[(size_t)(m0 + row0) * CC + col]     = make_float2(o0, o1);
            *(float2*)&outF[(size_t)(m0 + row0 + 8) * CC + col] = make_float2(o2, o3);
        } else {
            int colp = col >> 1;
            __nv_bfloat16 h0, l0, h1, l1;
            bfsplit(o0, h0, l0); bfsplit(o1, h1, l1);
            aoh[colp * ACT_STRIDE + row0] = pkbf(h0, h1);
            aol[colp * ACT_STRIDE + row0] = pkbf(l0, l1);
            bfsplit(o2, h0, l0); bfsplit(o3, h1, l1);
            aoh[colp * ACT_STRIDE + row0 + 8] = pkbf(h0, h1);
            aol[colp * ACT_STRIDE + row0 + 8] = pkbf(l0, l1);
        }
    }
    __syncthreads();   // act-out visible + wbuf safe for next layer
}

__global__ void __launch_bounds__(256) fused_mlp(
    const float* __restrict__ b1, const float* __restrict__ b2,
    const float* __restrict__ b3, const float* __restrict__ fb1,
    const float* __restrict__ fb2)
{
    extern __shared__ uint32_t sm[];
    uint32_t* A0h = sm + SM_A0H;
    uint32_t* A0l = sm + SM_A0L;
    uint32_t* A1h = sm + SM_A1H;
    uint32_t* A1l = sm + SM_A1L;
    uint32_t* WBh = sm + SM_WBH;
    uint32_t* WBl = sm + SM_WBL;
    int t = threadIdx.x;
    int m0 = blockIdx.x * 32;

    // load layer-1 input: 32 rows x 8 k2-pairs, transposed to [k2][m]
    {
        int m = t & 31, k2 = t >> 5;
        A0h[k2 * ACT_STRIDE + m] = a_gh[(size_t)(m0 + m) * 8 + k2];
        A0l[k2 * ACT_STRIDE + m] = a_gl[(size_t)(m0 + m) * 8 + k2];
    }
    __syncthreads();

    mlp_layer<8,   64,  true,  false>(A0h, A0l, A1h, A1l, WBh, WBl, w1h, w1l, b1,  nullptr,  m0, t);
    mlp_layer<32,  128, true,  false>(A1h, A1l, A0h, A0l, WBh, WBl, w2h, w2l, b2,  nullptr,  m0, t);
    mlp_layer<64,  256, false, false>(A0h, A0l, A1h, A1l, WBh, WBl, w3h, w3l, b3,  nullptr,  m0, t);
    mlp_layer<128, 256, true,  false>(A1h, A1l, A0h, A0l, WBh, WBl, f1h, f1l, fb1, nullptr,  m0, t);
    mlp_layer<128, 256, false, true >(A0h, A0l, A1h, A1l, WBh, WBl, f2h, f2l, fb2, g_featsT, m0, t);
}

// ---------------- tile render: 4 slices x 64 ch, bf16 2-split MMA -------------
__global__ void __launch_bounds__(256, 2) render_kernel(float* __restrict__ out) {
    int tile = blockIdx.x;
    int slice = blockIdx.y;
    int b = tile / TPB;
    int tl = tile % TPB;
    int tx0 = (tl % TBX) * TS;
    int ty0 = (tl / TBX) * TS;
    int t = threadIdx.x;
    int lx = t & 15;
    int ly = t >> 4;
    int lane = t & 31;
    int wid = t >> 5;
    int wm = wid & 1;
    int wn = wid >> 1;
    int g = lane >> 2;
    int c = lane & 3;

    __shared__ float s_px[16], s_py[16], s_isx[16], s_isy[16], s_w[16], s_as[16];
    __shared__ int   s_n[16];
    __shared__ float s_dx2[16][16], s_dy2[16][16], s_ex[16][16], s_ey[16][16];
    __shared__ uint32_t s_gwh[8][264], s_gwl[8][264];
    __shared__ uint32_t s_Fh[8][136], s_Fl[8][136];

    float* s_d = &s_dx2[0][0];

    float d[2][8][4];
    #pragma unroll
    for (int mt = 0; mt < 2; mt++)
        #pragma unroll
        for (int nt = 0; nt < 8; nt++)
            #pragma unroll
            for (int i = 0; i < 4; i++) d[mt][nt][i] = 0.f;
    float dacc = 0.f, uacc = 0.f;

    int K = g_tcount[tile];
    if (K > MAXG) K = MAXG;

    for (int c0 = 0; c0 < K; c0 += 16) {
        if (t < 16) {
            int idx = c0 + t;
            if (idx < K) {
                int n = g_tlist[tile * MAXG + idx];
                s_n[t] = n;
                s_px[t] = g_px[n];   s_py[t] = g_py[n];
                s_isx[t] = g_isx[n]; s_isy[t] = g_isy[n];
                s_w[t] = g_w[n];     s_as[t] = g_as[n];
            } else {
                s_n[t] = 0;
                s_px[t] = 3e8f; s_py[t] = 3e8f;
                s_isx[t] = 1.f; s_isy[t] = 1.f;
                s_w[t] = 0.f;   s_as[t] = 0.f;
            }
        }
        __syncthreads();
        // F slice: 16 gaussians x 64 channels -> bf16 pairs along j
        {
            int j2 = t >> 5;
            int ch2 = (t & 31) * 2;
            int ne = s_n[2 * j2], no = s_n[2 * j2 + 1];
            float2 fe = *(const float2*)&g_featsT[(size_t)ne * CC + slice * 64 + ch2];
            float2 fo = *(const float2*)&g_featsT[(size_t)no * CC + slice * 64 + ch2];
            __nv_bfloat16 he, le, ho, lo;
            bfsplit(fe.x, he, le); bfsplit(fo.x, ho, lo);
            s_Fh[j2][ch2]   = pkbf(he, ho);
            s_Fl[j2][ch2]   = pkbf(le, lo);
            bfsplit(fe.y, he, le); bfsplit(fo.y, ho, lo);
            s_Fh[j2][ch2+1] = pkbf(he, ho);
            s_Fl[j2][ch2+1] = pkbf(le, lo);
        }
        // separable exp
        {
            int j = t >> 4, i2 = t & 15;
            float dx = ((float)(tx0 + i2) - s_px[j]) * s_isx[j];
            float dx2 = dx * dx;
            s_dx2[j][i2] = dx2;
            s_ex[j][i2] = __expf(-0.5f * dx2);
            float dy = ((float)(ty0 + i2) - s_py[j]) * s_isy[j];
            float dy2 = dy * dy;
            s_dy2[j][i2] = dy2;
            s_ey[j][i2] = __expf(-0.5f * dy2);
        }
        __syncthreads();
        // gw for my pixel across 16 gaussians (exact fp32 density)
        #pragma unroll
        for (int j2 = 0; j2 < 8; j2++) {
            int j0 = 2 * j2, j1 = 2 * j2 + 1;
            float dd0 = s_dx2[j0][lx] + s_dy2[j0][ly];
            float dd1 = s_dx2[j1][lx] + s_dy2[j1][ly];
            float g0 = (dd0 < 9.0f) ? s_w[j0] * s_ex[j0][lx] * s_ey[j0][ly] : 0.0f;
            float g1 = (dd1 < 9.0f) ? s_w[j1] * s_ex[j1][lx] * s_ey[j1][ly] : 0.0f;
            dacc += g0 + g1;
            uacc += g0 * s_as[j0] + g1 * s_as[j1];
            __nv_bfloat16 h0, l0, h1, l1;
            bfsplit(g0, h0, l0); bfsplit(g1, h1, l1);
            s_gwh[j2][t] = pkbf(h0, h1);
            s_gwl[j2][t] = pkbf(l0, l1);
        }
        __syncthreads();
        // one k16 mma slab: 2 mt x 8 nt x 3 terms
        {
            uint32_t ah[2][4], al[2][4];
            #pragma unroll
            for (int mt = 0; mt < 2; mt++) {
                int m = wm * 32 + mt * 16 + g;
                ah[mt][0] = s_Fh[c][m];     ah[mt][1] = s_Fh[c][m + 8];
                ah[mt][2] = s_Fh[c+4][m];   ah[mt][3] = s_Fh[c+4][m + 8];
                al[mt][0] = s_Fl[c][m];     al[mt][1] = s_Fl[c][m + 8];
                al[mt][2] = s_Fl[c+4][m];   al[mt][3] = s_Fl[c+4][m + 8];
            }
            #pragma unroll
            for (int nt = 0; nt < 8; nt++) {
                int n = wn * 64 + nt * 8 + g;
                uint32_t bh0 = s_gwh[c][n],   bh1 = s_gwh[c+4][n];
                uint32_t bl0 = s_gwl[c][n],   bl1 = s_gwl[c+4][n];
                #pragma unroll
                for (int mt = 0; mt < 2; mt++) {
                    mma_bf16(d[mt][nt], ah[mt][0], ah[mt][1], ah[mt][2], ah[mt][3], bh0, bh1);
                    mma_bf16(d[mt][nt], al[mt][0], al[mt][1], al[mt][2], al[mt][3], bh0, bh1);
                    mma_bf16(d[mt][nt], ah[mt][0], ah[mt][1], ah[mt][2], ah[mt][3], bl0, bl1);
                }
            }
        }
        __syncthreads();
    }

    s_d[t] = dacc;
    __syncthreads();

    #pragma unroll
    for (int nt = 0; nt < 8; nt++) {
        int n = wn * 64 + nt * 8 + c * 2;
        float inv0 = 1.0f / fmaxf(s_d[n], 1e-6f);
        float inv1 = 1.0f / fmaxf(s_d[n + 1], 1e-6f);
        int py = n >> 4;
        int pxx = n & 15;
        #pragma unroll
        for (int mt = 0; mt < 2; mt++) {
            int ch = slice * 64 + wm * 32 + mt * 16 + g;
            float* r0 = out + (((size_t)(b * CC + ch) * HI + ty0 + py) * WI + tx0 + pxx);
            float* r1 = out + (((size_t)(b * CC + ch + 8) * HI + ty0 + py) * WI + tx0 + pxx);
            *(float2*)r0 = make_float2(d[mt][nt][0] * inv0, d[mt][nt][1] * inv1);
            *(float2*)r1 = make_float2(d[mt][nt][2] * inv0, d[mt][nt][3] * inv1);
        }
    }
    if (slice == 0) {
        int pix = (ty0 + ly) * WI + tx0 + lx;
        float dv = fmaxf(dacc, 1e-6f);
        out[FM_SIZE + b * HW + pix] = uacc / dv;
        out[FM_SIZE + BB * HW + b * HW + pix] = dv;
    }
}

// ---------------- launch ----------------
extern "C" void kernel_launch(void* const* d_in, const int* in_sizes, int n_in,
                              void* d_out, int out_size) {
    const float* g      = (const float*)d_in[0];
    const float* intr   = (const float*)d_in[1];
    const float* enc_w1 = (const float*)d_in[2];
    const float* enc_b1 = (const float*)d_in[3];
    const float* enc_w2 = (const float*)d_in[4];
    const float* enc_b2 = (const float*)d_in[5];
    const float* enc_w3 = (const float*)d_in[6];
    const float* enc_b3 = (const float*)d_in[7];
    const float* ft_w1  = (const float*)d_in[8];
    const float* ft_b1  = (const float*)d_in[9];
    const float* ft_w2  = (const float*)d_in[10];
    const float* ft_b2  = (const float*)d_in[11];
    float* out = (float*)d_out;

    int* ptc;
    cudaGetSymbolAddress((void**)&ptc, g_tcount);

    cudaFuncSetAttribute(fused_mlp, cudaFuncAttributeMaxDynamicSharedMemorySize,
                         MLP_SMEM_BYTES);

    cudaMemsetAsync(ptc, 0, NT * sizeof(int));
    prep_all<<<(PREP_TOTAL + 255) / 256, 256>>>(g, enc_w1, enc_w2, enc_w3, ft_w1, ft_w2);
    proj_bin_kernel<<<(BN + 255) / 256, 256>>>(g, intr);
    fused_mlp<<<BN / 32, 256, MLP_SMEM_BYTES>>>(enc_b1, enc_b2, enc_b3, ft_b1, ft_b2);
    render_kernel<<<dim3(NT, 4), 256>>>(out);
}